// round 10
// baseline (speedup 1.0000x reference)
#include <cuda_runtime.h>
#include <math.h>

// Tropical (max-plus) depthwise 5x5 conv, stride 1, pad 2 (-inf), dilation 1.
// x: [8,32,224,224] f32, kernel: [32,1,5,5] f32, out same shape.
// out[b,c,h,w] = max_{i,j} ( x_pad[b,c,h+i,w+j] + kflip[c,i,j] ),
// kflip[c,i,j] = kernel[c,0,4-i,4-j].
//
// R8 = R7 + register diet for occupancy:
//  - Flipped weights live in SMEM (2 plane slots: a 256-thread block can
//    straddle at most 2 planes since 256 < 1596). Each (r,i) tap block
//    reloads its 5 weights via volatile LDS (volatile blocks ptxas CSE that
//    would re-materialize all 25 in registers). ~25 regs freed.
//  - __launch_bounds__(256,5): 51-reg target -> 5 CTAs/SM (40 warps).
//  - Otherwise identical to the 33.3us kernel: 4-wide x 8-tall streaming
//    tile, cyclic 5-row accumulator window, balanced max trees with the
//    i==0 init fusion, 2 aligned float4 loads/row, predicated float2 stores,
//    57 col-groups x 28 row-groups x 256 planes, 1596 blocks of 256.

#define HW 224
#define NEG_INF (-INFINITY)

__global__ __launch_bounds__(256, 5) void tropical_conv_kernel(
    const float* __restrict__ x,
    const float* __restrict__ w,
    float* __restrict__ out)
{
    __shared__ float swf[2][28];            // [plane slot][i*5+j], padded

    const int tid   = threadIdx.x;
    const int gid0  = blockIdx.x * 256;
    const int gid   = gid0 + tid;
    const int plane0 = gid0 / 1596;         // plane of thread 0 of this block
    const int plane  = gid / 1596;          // b*32 + c, 0..255
    const int rem    = gid - plane * 1596;
    const int rg     = rem / 57;            // row group 0..27 (output rows rg*8..)
    const int tx     = rem - rg * 57;       // col group 0..56

    // Stage flipped weights for the (up to) 2 planes this block touches.
    if (tid < 50) {
        const int p  = tid / 25;            // plane slot 0/1
        const int k  = tid - p * 25;        // 0..24
        const int i  = k / 5;
        const int j  = k - i * 5;
        const int cp = ((gid0 + p * 255) / 1596) & 31;
        swf[p][k] = w[cp * 25 + (4 - i) * 5 + (4 - j)];
    }
    __syncthreads();

    // volatile: force LDS at each use instead of CSE back into registers.
    volatile const float* wb = swf[plane - plane0];

    const float* xp = x + (size_t)plane * (HW * HW);
    float* op_base  = out + (size_t)plane * (HW * HW) + (rg * 8) * HW + (tx * 4 - 2);

    const int colL = tx * 4 - 4;            // left aligned quad: cols colL..colL+3
    const int row0 = rg * 8 - 2;            // first input row of the 12-row window

    const bool ldL = (tx > 0);
    const bool ldR = (tx < 56);

    float acc[5][4];                        // cyclic window of 5 active output rows

#pragma unroll
    for (int r = 0; r < 12; r++) {
        const int gr = row0 + r;
        const bool rowok = (gr >= 0) && (gr < HW);

        float v[8];                         // input cols colL .. colL+7
        if (rowok) {
            const float* rowp = xp + gr * HW + colL;
            if (ldL) {
                const float4 t = *reinterpret_cast<const float4*>(rowp);
                v[0] = t.x; v[1] = t.y; v[2] = t.z; v[3] = t.w;
            } else {
                v[0] = NEG_INF; v[1] = NEG_INF; v[2] = NEG_INF; v[3] = NEG_INF;
            }
            if (ldR) {
                const float4 t = *reinterpret_cast<const float4*>(rowp + 4);
                v[4] = t.x; v[5] = t.y; v[6] = t.z; v[7] = t.w;
            } else {
                v[4] = NEG_INF; v[5] = NEG_INF; v[6] = NEG_INF; v[7] = NEG_INF;
            }
        } else {
#pragma unroll
            for (int q = 0; q < 8; q++) v[q] = NEG_INF;
        }

        // Input row r contributes to output rows oh = r - i, i = 0..4.
        // i == 0 (oh == r) is that output row's FIRST contribution: assign
        // the tree result directly (no -inf init, no extra max).
#pragma unroll
        for (int i = 0; i < 5; i++) {
            const int oh = r - i;
            if (oh >= 0 && oh < 8) {        // compile-time after unroll
                const int s = oh % 5;
                const float w0 = wb[i * 5 + 0];
                const float w1 = wb[i * 5 + 1];
                const float w2 = wb[i * 5 + 2];
                const float w3 = wb[i * 5 + 3];
                const float w4 = wb[i * 5 + 4];
#pragma unroll
                for (int q = 0; q < 4; q++) {
                    const float t0 = v[q + 0] + w0;
                    const float t1 = v[q + 1] + w1;
                    const float t2 = v[q + 2] + w2;
                    const float t3 = v[q + 3] + w3;
                    const float t4 = v[q + 4] + w4;
                    const float m  = fmaxf(fmaxf(t0, t1), t2);
                    if (i == 0) {
                        acc[s][q] = fmaxf(m, fmaxf(t3, t4));
                    } else {
                        const float n = fmaxf(fmaxf(t3, t4), acc[s][q]);
                        acc[s][q] = fmaxf(m, n);
                    }
                }
            }
        }

        // Output row oh = r - 4 is complete after this input row: store it.
        if (r >= 4) {
            const int oh = r - 4;
            const int s  = oh % 5;
            float* orow  = op_base + oh * HW;
            if (tx > 0) {
                float2 t; t.x = acc[s][0]; t.y = acc[s][1];
                *reinterpret_cast<float2*>(orow) = t;
            }
            if (tx < 56) {
                float2 t; t.x = acc[s][2]; t.y = acc[s][3];
                *reinterpret_cast<float2*>(orow + 2) = t;
            }
        }
    }
}

extern "C" void kernel_launch(void* const* d_in, const int* in_sizes, int n_in,
                              void* d_out, int out_size)
{
    const float* x = (const float*)d_in[0];
    const float* w = (const float*)d_in[1];
    float* out     = (float*)d_out;
    // 256 planes * 28 row-groups * 57 col-groups = 408576 threads = 1596 blocks
    tropical_conv_kernel<<<1596, 256>>>(x, w, out);
}